// round 1
// baseline (speedup 1.0000x reference)
#include <cuda_runtime.h>

#define HID 4096
#define KVD 1024
#define SEQ 2048
#define NHEADS 32
#define NKVH 8
#define HD 128

// ---------------- scratch (static device allocations) ----------------
__device__ float g_wmq[HID * HID];
__device__ float g_wmo[HID * HID];
__device__ float g_wmk[KVD * HID];
__device__ float g_wmv[KVD * HID];
__device__ float g_q[SEQ * HID];
__device__ float g_k[SEQ * KVD];
__device__ float g_v[SEQ * KVD];
__device__ float g_ao[SEQ * HID];
__device__ int   g_invp_qkv[HID];
__device__ int   g_invp_o[HID];

// ---------------- permutation extraction ----------------
// perm[i,j] = 1 iff j == p[i].  invp[j] = i  (source column feeding permuted col j)
__global__ void perm_extract(const float* __restrict__ P, int* __restrict__ invp, int n) {
    int idx = blockIdx.x * blockDim.x + threadIdx.x;
    if (idx >= n * n) return;
    if (P[idx] > 0.5f) invp[idx % n] = idx / n;
}

// ---------------- 2:4 hard mask (wanda metric, permuted groups) ----------------
__global__ void mask_weights(const float* __restrict__ W, const float* __restrict__ scaler,
                             const int* __restrict__ invp, float* __restrict__ Wm,
                             int R, int H) {
    int idx = blockIdx.x * blockDim.x + threadIdx.x;
    int G = H >> 2;
    if (idx >= R * G) return;
    int r = idx / G, g = idx % G;
    int c[4]; float w[4], m[4];
#pragma unroll
    for (int t = 0; t < 4; t++) {
        c[t] = invp[4 * g + t];
        w[t] = W[r * H + c[t]];
        m[t] = fabsf(w[t]) * sqrtf(scaler[c[t]]);
    }
#pragma unroll
    for (int t = 0; t < 4; t++) {
        int rank = 0;
#pragma unroll
        for (int u = 0; u < 4; u++)
            rank += (m[u] > m[t]) || (m[u] == m[t] && u < t);
        Wm[r * H + c[t]] = (rank < 2) ? w[t] : 0.0f;
    }
}

// ---------------- fp32 NT GEMM: C[M,N] = A[M,K] * B[N,K]^T ----------------
// 128x128 tile, BK=16, 256 threads, 8x8 microtile.
__global__ void __launch_bounds__(256) gemm_nt(const float* __restrict__ A,
                                               const float* __restrict__ B,
                                               float* __restrict__ C,
                                               int M, int N, int K) {
    __shared__ float As[16][132];
    __shared__ float Bs[16][132];
    const int tid = threadIdx.x;
    const int tx = tid & 15, ty = tid >> 4;
    const int bm = blockIdx.y * 128, bn = blockIdx.x * 128;
    const int lr = tid >> 2, lc = tid & 3;

    float acc[8][8];
#pragma unroll
    for (int i = 0; i < 8; i++)
#pragma unroll
        for (int j = 0; j < 8; j++) acc[i][j] = 0.f;

    const float* Aptr = A + (size_t)(bm + lr) * K + lc * 4;
    const float* Bptr = B + (size_t)(bn + lr) * K + lc * 4;

    for (int k0 = 0; k0 < K; k0 += 16) {
        float4 a0 = *(const float4*)(Aptr + k0);
        float4 a1 = *(const float4*)(Aptr + (size_t)64 * K + k0);
        float4 b0 = *(const float4*)(Bptr + k0);
        float4 b1 = *(const float4*)(Bptr + (size_t)64 * K + k0);
        __syncthreads();
        As[lc * 4 + 0][lr] = a0.x; As[lc * 4 + 1][lr] = a0.y;
        As[lc * 4 + 2][lr] = a0.z; As[lc * 4 + 3][lr] = a0.w;
        As[lc * 4 + 0][lr + 64] = a1.x; As[lc * 4 + 1][lr + 64] = a1.y;
        As[lc * 4 + 2][lr + 64] = a1.z; As[lc * 4 + 3][lr + 64] = a1.w;
        Bs[lc * 4 + 0][lr] = b0.x; Bs[lc * 4 + 1][lr] = b0.y;
        Bs[lc * 4 + 2][lr] = b0.z; Bs[lc * 4 + 3][lr] = b0.w;
        Bs[lc * 4 + 0][lr + 64] = b1.x; Bs[lc * 4 + 1][lr + 64] = b1.y;
        Bs[lc * 4 + 2][lr + 64] = b1.z; Bs[lc * 4 + 3][lr + 64] = b1.w;
        __syncthreads();
#pragma unroll
        for (int kk = 0; kk < 16; kk++) {
            float4 av0 = *(const float4*)&As[kk][ty * 8];
            float4 av1 = *(const float4*)&As[kk][ty * 8 + 4];
            float4 bv0 = *(const float4*)&Bs[kk][tx * 8];
            float4 bv1 = *(const float4*)&Bs[kk][tx * 8 + 4];
            float a[8] = {av0.x, av0.y, av0.z, av0.w, av1.x, av1.y, av1.z, av1.w};
            float b[8] = {bv0.x, bv0.y, bv0.z, bv0.w, bv1.x, bv1.y, bv1.z, bv1.w};
#pragma unroll
            for (int i = 0; i < 8; i++)
#pragma unroll
                for (int j = 0; j < 8; j++)
                    acc[i][j] = fmaf(a[i], b[j], acc[i][j]);
        }
    }
#pragma unroll
    for (int i = 0; i < 8; i++) {
        float4 o0 = make_float4(acc[i][0], acc[i][1], acc[i][2], acc[i][3]);
        float4 o1 = make_float4(acc[i][4], acc[i][5], acc[i][6], acc[i][7]);
        float* cp = C + (size_t)(bm + ty * 8 + i) * N + bn + tx * 8;
        *(float4*)(cp) = o0;
        *(float4*)(cp + 4) = o1;
    }
}

// ---------------- RoPE (in place, paired halves) ----------------
__global__ void rope_kernel(float* __restrict__ X, const float* __restrict__ cosT,
                            const float* __restrict__ sinT, int nheads) {
    int idx = blockIdx.x * blockDim.x + threadIdx.x;
    int total = SEQ * nheads * 64;
    if (idx >= total) return;
    int d = idx & 63;
    int h = (idx >> 6) % nheads;
    int s = idx / (64 * nheads);
    float* p = X + (size_t)s * nheads * HD + h * HD + d;
    float x1 = p[0], x2 = p[64];
    float c1 = cosT[s * HD + d],      s1 = sinT[s * HD + d];
    float c2 = cosT[s * HD + 64 + d], s2 = sinT[s * HD + 64 + d];
    p[0]  = fmaf(x1, c1, -x2 * s1);
    p[64] = fmaf(x2, c2,  x1 * s2);
}

// ---------------- causal flash attention, fp32 ----------------
// One CTA: (head, 64 q rows). 256 threads. K blocks of 64, causal skip.
#define FL_SMEM_FLOATS (128*68 + 128*68 + 64*132 + 64*65 + 64*17 + 4*64)

__global__ void __launch_bounds__(256) flash_kernel(const float* __restrict__ Qg,
                                                    const float* __restrict__ Kg,
                                                    const float* __restrict__ Vg,
                                                    float* __restrict__ Og) {
    extern __shared__ float sm[];
    float* Qst  = sm;                 // [128][68] (transposed: [d][row])
    float* Kst  = Qst + 128 * 68;     // [128][68]
    float* Vs   = Kst + 128 * 68;     // [64][132]
    float* Ss   = Vs + 64 * 132;      // [64][65]  scores -> P
    float* part = Ss + 64 * 65;       // [64][17]  row-sum partials
    float* mrow = part + 64 * 17;     // [64]
    float* lrow = mrow + 64;
    float* fsc  = lrow + 64;
    float* mnew = fsc + 64;

    const int tid = threadIdx.x;
    const int qb = blockIdx.x;
    const int head = blockIdx.y;
    const int kvh = head >> 2;
    const float* Qh = Qg + head * HD;   // row stride HID
    const float* Kh = Kg + kvh * HD;    // row stride KVD
    const float* Vh = Vg + kvh * HD;

    // load Q tile (transposed)
#pragma unroll
    for (int i = 0; i < 8; i++) {
        int lin = tid + i * 256;
        int r = lin >> 5, c4 = lin & 31;
        float4 qv = *(const float4*)&Qh[(size_t)(qb * 64 + r) * HID + c4 * 4];
        Qst[(c4 * 4 + 0) * 68 + r] = qv.x;
        Qst[(c4 * 4 + 1) * 68 + r] = qv.y;
        Qst[(c4 * 4 + 2) * 68 + r] = qv.z;
        Qst[(c4 * 4 + 3) * 68 + r] = qv.w;
    }
    if (tid < 64) { mrow[tid] = -1e30f; lrow[tid] = 0.f; }

    float acc[32];
#pragma unroll
    for (int i = 0; i < 32; i++) acc[i] = 0.f;

    const int tx = tid & 15, ty = tid >> 4;       // phase A 4x4 map
    const int qr = tid >> 2, chunk = tid & 3;     // phase B map
    const float scale = 0.08838834764831845f;     // 1/sqrt(128)

    for (int kb = 0; kb <= qb; kb++) {
        __syncthreads();   // prev iter done reading Kst/Vs/Ss/part
        // load K (transposed) and V (row major)
#pragma unroll
        for (int i = 0; i < 8; i++) {
            int lin = tid + i * 256;
            int r = lin >> 5, c4 = lin & 31;
            float4 kv = *(const float4*)&Kh[(size_t)(kb * 64 + r) * KVD + c4 * 4];
            Kst[(c4 * 4 + 0) * 68 + r] = kv.x;
            Kst[(c4 * 4 + 1) * 68 + r] = kv.y;
            Kst[(c4 * 4 + 2) * 68 + r] = kv.z;
            Kst[(c4 * 4 + 3) * 68 + r] = kv.w;
            float4 vv = *(const float4*)&Vh[(size_t)(kb * 64 + r) * KVD + c4 * 4];
            *(float4*)&Vs[r * 132 + c4 * 4] = vv;
        }
        __syncthreads();

        // phase A: 64x64 scores, 4x4 per thread
        float sreg[4][4];
#pragma unroll
        for (int i = 0; i < 4; i++)
#pragma unroll
            for (int j = 0; j < 4; j++) sreg[i][j] = 0.f;
#pragma unroll 8
        for (int kk = 0; kk < 128; kk++) {
            float4 av = *(const float4*)&Qst[kk * 68 + ty * 4];
            float4 bv = *(const float4*)&Kst[kk * 68 + tx * 4];
            float a[4] = {av.x, av.y, av.z, av.w};
            float b[4] = {bv.x, bv.y, bv.z, bv.w};
#pragma unroll
            for (int i = 0; i < 4; i++)
#pragma unroll
                for (int j = 0; j < 4; j++)
                    sreg[i][j] = fmaf(a[i], b[j], sreg[i][j]);
        }
        bool diag = (kb == qb);
#pragma unroll
        for (int i = 0; i < 4; i++)
#pragma unroll
            for (int j = 0; j < 4; j++) {
                float sv = sreg[i][j] * scale;
                if (diag && (tx * 4 + j) > (ty * 4 + i)) sv = -1e30f;
                sreg[i][j] = sv;
                Ss[(ty * 4 + i) * 65 + tx * 4 + j] = sv;
            }
        __syncthreads();

        // row max (64 threads)
        if (tid < 64) {
            float mx = -1e30f;
            for (int c = 0; c < 64; c++) mx = fmaxf(mx, Ss[tid * 65 + c]);
            float mo = mrow[tid];
            float mn = fmaxf(mo, mx);
            mnew[tid] = mn;
            fsc[tid] = __expf(mo - mn);
        }
        __syncthreads();

        // exp + write P + row-sum partials
        float psum[4] = {0.f, 0.f, 0.f, 0.f};
#pragma unroll
        for (int i = 0; i < 4; i++) {
            float mn = mnew[ty * 4 + i];
#pragma unroll
            for (int j = 0; j < 4; j++) {
                float p = __expf(sreg[i][j] - mn);
                Ss[(ty * 4 + i) * 65 + tx * 4 + j] = p;
                psum[i] += p;
            }
        }
#pragma unroll
        for (int i = 0; i < 4; i++) part[(ty * 4 + i) * 17 + tx] = psum[i];
        __syncthreads();

        if (tid < 64) {
            float s = 0.f;
            for (int x = 0; x < 16; x++) s += part[tid * 17 + x];
            lrow[tid] = lrow[tid] * fsc[tid] + s;
            mrow[tid] = mnew[tid];
        }

        // phase B: acc = acc*f + P @ V  (each thread: 1 q row, 32 dims)
        float f = fsc[qr];
#pragma unroll
        for (int d = 0; d < 32; d++) acc[d] *= f;
        for (int kkk = 0; kkk < 64; kkk++) {
            float p = Ss[qr * 65 + kkk];
            const float* vr = &Vs[kkk * 132 + chunk * 32];
#pragma unroll
            for (int dd = 0; dd < 8; dd++) {
                float4 vv = *(const float4*)(vr + dd * 4);
                acc[dd * 4 + 0] = fmaf(p, vv.x, acc[dd * 4 + 0]);
                acc[dd * 4 + 1] = fmaf(p, vv.y, acc[dd * 4 + 1]);
                acc[dd * 4 + 2] = fmaf(p, vv.z, acc[dd * 4 + 2]);
                acc[dd * 4 + 3] = fmaf(p, vv.w, acc[dd * 4 + 3]);
            }
        }
    }
    __syncthreads();   // lrow final
    float linv = 1.f / lrow[qr];
    float* op = Og + (size_t)(qb * 64 + qr) * HID + head * HD + chunk * 32;
#pragma unroll
    for (int dd = 0; dd < 8; dd++) {
        float4 o = make_float4(acc[dd * 4 + 0] * linv, acc[dd * 4 + 1] * linv,
                               acc[dd * 4 + 2] * linv, acc[dd * 4 + 3] * linv);
        *(float4*)(op + dd * 4) = o;
    }
}

// ---------------- launch ----------------
extern "C" void kernel_launch(void* const* d_in, const int* in_sizes, int n_in,
                              void* d_out, int out_size) {
    const float* hs   = (const float*)d_in[0];
    const float* wq   = (const float*)d_in[1];
    const float* wk   = (const float*)d_in[2];
    const float* wv   = (const float*)d_in[3];
    const float* wo   = (const float*)d_in[4];
    const float* scq  = (const float*)d_in[5];
    const float* sck  = (const float*)d_in[6];
    const float* scv  = (const float*)d_in[7];
    const float* sco  = (const float*)d_in[8];
    const float* pqkv = (const float*)d_in[9];
    const float* po   = (const float*)d_in[10];
    const float* cosT = (const float*)d_in[11];
    const float* sinT = (const float*)d_in[12];
    float* out = (float*)d_out;

    float *wmq, *wmk, *wmv, *wmo, *q, *k, *v, *ao;
    int *ipq, *ipo;
    cudaGetSymbolAddress((void**)&wmq, g_wmq);
    cudaGetSymbolAddress((void**)&wmk, g_wmk);
    cudaGetSymbolAddress((void**)&wmv, g_wmv);
    cudaGetSymbolAddress((void**)&wmo, g_wmo);
    cudaGetSymbolAddress((void**)&q,   g_q);
    cudaGetSymbolAddress((void**)&k,   g_k);
    cudaGetSymbolAddress((void**)&v,   g_v);
    cudaGetSymbolAddress((void**)&ao,  g_ao);
    cudaGetSymbolAddress((void**)&ipq, g_invp_qkv);
    cudaGetSymbolAddress((void**)&ipo, g_invp_o);

    // permutations
    perm_extract<<<(HID * HID + 255) / 256, 256>>>(pqkv, ipq, HID);
    perm_extract<<<(HID * HID + 255) / 256, 256>>>(po,   ipo, HID);

    // masked weights
    mask_weights<<<(HID * (HID / 4) + 255) / 256, 256>>>(wq, scq, ipq, wmq, HID, HID);
    mask_weights<<<(KVD * (HID / 4) + 255) / 256, 256>>>(wk, sck, ipq, wmk, KVD, HID);
    mask_weights<<<(KVD * (HID / 4) + 255) / 256, 256>>>(wv, scv, ipq, wmv, KVD, HID);
    mask_weights<<<(HID * (HID / 4) + 255) / 256, 256>>>(wo, sco, ipo, wmo, HID, HID);

    // projections
    gemm_nt<<<dim3(HID / 128, SEQ / 128), 256>>>(hs, wmq, q, SEQ, HID, HID);
    gemm_nt<<<dim3(KVD / 128, SEQ / 128), 256>>>(hs, wmk, k, SEQ, KVD, HID);
    gemm_nt<<<dim3(KVD / 128, SEQ / 128), 256>>>(hs, wmv, v, SEQ, KVD, HID);

    // rope
    rope_kernel<<<(SEQ * NHEADS * 64 + 255) / 256, 256>>>(q, cosT, sinT, NHEADS);
    rope_kernel<<<(SEQ * NKVH * 64 + 255) / 256, 256>>>(k, cosT, sinT, NKVH);

    // attention
    int fl_smem = FL_SMEM_FLOATS * (int)sizeof(float);
    cudaFuncSetAttribute(flash_kernel, cudaFuncAttributeMaxDynamicSharedMemorySize, fl_smem);
    flash_kernel<<<dim3(SEQ / 64, NHEADS), 256, fl_smem>>>(q, k, v, ao);

    // output projection -> d_out
    gemm_nt<<<dim3(HID / 128, SEQ / 128), 256>>>(ao, wmo, out, SEQ, HID, HID);
}

// round 2
// speedup vs baseline: 1.4013x; 1.4013x over previous
#include <cuda_runtime.h>
#include <cstdint>

#define HID 4096
#define KVD 1024
#define SEQ 2048
#define NHEADS 32
#define NKVH 8
#define HD 128

// ---------------- scratch (static device allocations) ----------------
__device__ float g_wmq[HID * HID];
__device__ float g_wmo[HID * HID];
__device__ float g_wmk[KVD * HID];
__device__ float g_wmv[KVD * HID];
__device__ float g_hst[SEQ * HID];
__device__ float g_q[SEQ * HID];
__device__ float g_k[SEQ * KVD];
__device__ float g_v[SEQ * KVD];
__device__ float g_ao[SEQ * HID];
__device__ int   g_invp_qkv[HID];
__device__ int   g_invp_o[HID];

__device__ __forceinline__ float tf32_rna(float x) {
    uint32_t u;
    asm("cvt.rna.tf32.f32 %0, %1;" : "=r"(u) : "f"(x));
    return __uint_as_float(u);
}

// ---------------- permutation extraction ----------------
__global__ void perm_extract(const float* __restrict__ P, int* __restrict__ invp, int n) {
    int idx = blockIdx.x * blockDim.x + threadIdx.x;
    if (idx >= n * n) return;
    if (P[idx] > 0.5f) invp[idx % n] = idx / n;
}

// ---------------- round hidden states to tf32 ----------------
__global__ void round_tf32(const float* __restrict__ X, float* __restrict__ Y, int n4) {
    int idx = blockIdx.x * blockDim.x + threadIdx.x;
    if (idx >= n4) return;
    float4 v = ((const float4*)X)[idx];
    v.x = tf32_rna(v.x); v.y = tf32_rna(v.y);
    v.z = tf32_rna(v.z); v.w = tf32_rna(v.w);
    ((float4*)Y)[idx] = v;
}

// ---------------- 2:4 hard mask (wanda metric, permuted groups) ----------------
// Output is tf32-rounded so the tf32 GEMM sees round-to-nearest operands.
__global__ void mask_weights(const float* __restrict__ W, const float* __restrict__ scaler,
                             const int* __restrict__ invp, float* __restrict__ Wm,
                             int R, int H) {
    int idx = blockIdx.x * blockDim.x + threadIdx.x;
    int G = H >> 2;
    if (idx >= R * G) return;
    int r = idx / G, g = idx % G;
    int c[4]; float w[4], m[4];
#pragma unroll
    for (int t = 0; t < 4; t++) {
        c[t] = invp[4 * g + t];
        w[t] = W[r * H + c[t]];
        m[t] = fabsf(w[t]) * sqrtf(scaler[c[t]]);
    }
#pragma unroll
    for (int t = 0; t < 4; t++) {
        int rank = 0;
#pragma unroll
        for (int u = 0; u < 4; u++)
            rank += (m[u] > m[t]) || (m[u] == m[t] && u < t);
        Wm[r * H + c[t]] = (rank < 2) ? tf32_rna(w[t]) : 0.0f;
    }
}

// ---------------- tf32 tensor-core NT GEMM: C[M,N] = A[M,K] * B[N,K]^T ----------
// 128x128x32 CTA tile, 256 threads (2x4 warps, 64x32 warp tiles),
// double-buffered cp.async, mma.sync.m16n8k8.tf32.
#define GS 36                      // smem row stride (floats): conflict-free frag loads
#define STAGE_F (128 * GS)         // floats per stage per operand
#define GEMM_SMEM_BYTES (4 * STAGE_F * 4)

__device__ __forceinline__ void mma_tf32(float c[4], uint32_t a0, uint32_t a1,
                                         uint32_t a2, uint32_t a3,
                                         uint32_t b0, uint32_t b1) {
    asm volatile(
        "mma.sync.aligned.m16n8k8.row.col.f32.tf32.tf32.f32 "
        "{%0,%1,%2,%3}, {%4,%5,%6,%7}, {%8,%9}, {%0,%1,%2,%3};"
        : "+f"(c[0]), "+f"(c[1]), "+f"(c[2]), "+f"(c[3])
        : "r"(a0), "r"(a1), "r"(a2), "r"(a3), "r"(b0), "r"(b1));
}

__global__ void __launch_bounds__(256) gemm_tf32(const float* __restrict__ A,
                                                 const float* __restrict__ B,
                                                 float* __restrict__ C,
                                                 int M, int N, int K) {
    extern __shared__ float sm[];
    float* As = sm;                    // [2][128][GS]
    float* Bs = sm + 2 * STAGE_F;      // [2][128][GS]

    const int tid = threadIdx.x;
    const int wid = tid >> 5, lane = tid & 31;
    const int g = lane >> 2, tg = lane & 3;
    const int wm = (wid >> 2) * 64, wn = (wid & 3) * 32;
    const int bm = blockIdx.y * 128, bn = blockIdx.x * 128;
    const int ar = tid >> 3, ac = (tid & 7) * 4;

    float acc[4][4][4] = {};

    const float* Ag = A + (size_t)(bm + ar) * K + ac;
    const float* Bg = B + (size_t)(bn + ar) * K + ac;

    uint32_t sA = (uint32_t)__cvta_generic_to_shared(As);
    uint32_t sB = (uint32_t)__cvta_generic_to_shared(Bs);

#define LOAD_STAGE(s, k0)                                                        \
    do {                                                                         \
        uint32_t soff = (uint32_t)(s) * STAGE_F * 4;                             \
        _Pragma("unroll")                                                        \
        for (int i = 0; i < 4; i++) {                                            \
            uint32_t da = sA + soff + ((ar + i * 32) * GS + ac) * 4;             \
            uint32_t db = sB + soff + ((ar + i * 32) * GS + ac) * 4;             \
            const float* pa = Ag + (size_t)i * 32 * K + (k0);                    \
            const float* pb = Bg + (size_t)i * 32 * K + (k0);                    \
            asm volatile("cp.async.cg.shared.global [%0], [%1], 16;" ::"r"(da), "l"(pa)); \
            asm volatile("cp.async.cg.shared.global [%0], [%1], 16;" ::"r"(db), "l"(pb)); \
        }                                                                        \
    } while (0)

    LOAD_STAGE(0, 0);
    asm volatile("cp.async.commit_group;");

    const int nk = K >> 5;
    for (int t = 0; t < nk; t++) {
        int s = t & 1;
        if (t + 1 < nk) LOAD_STAGE(s ^ 1, (t + 1) * 32);
        asm volatile("cp.async.commit_group;");
        asm volatile("cp.async.wait_group 1;");
        __syncthreads();

        const float* Ast = As + s * STAGE_F;
        const float* Bst = Bs + s * STAGE_F;
#pragma unroll
        for (int kk = 0; kk < 32; kk += 8) {
            uint32_t bf[4][2];
#pragma unroll
            for (int ni = 0; ni < 4; ni++) {
                int rn = (wn + ni * 8 + g) * GS + kk + tg;
                bf[ni][0] = __float_as_uint(Bst[rn]);
                bf[ni][1] = __float_as_uint(Bst[rn + 4]);
            }
#pragma unroll
            for (int mi = 0; mi < 4; mi++) {
                int rm = (wm + mi * 16 + g) * GS + kk + tg;
                uint32_t a0 = __float_as_uint(Ast[rm]);
                uint32_t a1 = __float_as_uint(Ast[rm + 8 * GS]);
                uint32_t a2 = __float_as_uint(Ast[rm + 4]);
                uint32_t a3 = __float_as_uint(Ast[rm + 8 * GS + 4]);
#pragma unroll
                for (int ni = 0; ni < 4; ni++)
                    mma_tf32(acc[mi][ni], a0, a1, a2, a3, bf[ni][0], bf[ni][1]);
            }
        }
        __syncthreads();
    }

#pragma unroll
    for (int mi = 0; mi < 4; mi++)
#pragma unroll
        for (int ni = 0; ni < 4; ni++) {
            int row = bm + wm + mi * 16 + g;
            int col = bn + wn + ni * 8 + tg * 2;
            *(float2*)&C[(size_t)row * N + col] =
                make_float2(acc[mi][ni][0], acc[mi][ni][1]);
            *(float2*)&C[(size_t)(row + 8) * N + col] =
                make_float2(acc[mi][ni][2], acc[mi][ni][3]);
        }
#undef LOAD_STAGE
}

// ---------------- RoPE (in place, paired halves) ----------------
__global__ void rope_kernel(float* __restrict__ X, const float* __restrict__ cosT,
                            const float* __restrict__ sinT, int nheads) {
    int idx = blockIdx.x * blockDim.x + threadIdx.x;
    int total = SEQ * nheads * 64;
    if (idx >= total) return;
    int d = idx & 63;
    int h = (idx >> 6) % nheads;
    int s = idx / (64 * nheads);
    float* p = X + (size_t)s * nheads * HD + h * HD + d;
    float x1 = p[0], x2 = p[64];
    float c1 = cosT[s * HD + d],      s1 = sinT[s * HD + d];
    float c2 = cosT[s * HD + 64 + d], s2 = sinT[s * HD + 64 + d];
    p[0]  = fmaf(x1, c1, -x2 * s1);
    p[64] = fmaf(x2, c2,  x1 * s2);
}

// ---------------- causal flash attention, fp32 ----------------
#define FL_SMEM_FLOATS (128*68 + 128*68 + 64*132 + 64*65 + 64*17 + 4*64)

__global__ void __launch_bounds__(256) flash_kernel(const float* __restrict__ Qg,
                                                    const float* __restrict__ Kg,
                                                    const float* __restrict__ Vg,
                                                    float* __restrict__ Og) {
    extern __shared__ float sm[];
    float* Qst  = sm;
    float* Kst  = Qst + 128 * 68;
    float* Vs   = Kst + 128 * 68;
    float* Ss   = Vs + 64 * 132;
    float* part = Ss + 64 * 65;
    float* mrow = part + 64 * 17;
    float* lrow = mrow + 64;
    float* fsc  = lrow + 64;
    float* mnew = fsc + 64;

    const int tid = threadIdx.x;
    const int qb = blockIdx.x;
    const int head = blockIdx.y;
    const int kvh = head >> 2;
    const float* Qh = Qg + head * HD;
    const float* Kh = Kg + kvh * HD;
    const float* Vh = Vg + kvh * HD;

#pragma unroll
    for (int i = 0; i < 8; i++) {
        int lin = tid + i * 256;
        int r = lin >> 5, c4 = lin & 31;
        float4 qv = *(const float4*)&Qh[(size_t)(qb * 64 + r) * HID + c4 * 4];
        Qst[(c4 * 4 + 0) * 68 + r] = qv.x;
        Qst[(c4 * 4 + 1) * 68 + r] = qv.y;
        Qst[(c4 * 4 + 2) * 68 + r] = qv.z;
        Qst[(c4 * 4 + 3) * 68 + r] = qv.w;
    }
    if (tid < 64) { mrow[tid] = -1e30f; lrow[tid] = 0.f; }

    float acc[32];
#pragma unroll
    for (int i = 0; i < 32; i++) acc[i] = 0.f;

    const int tx = tid & 15, ty = tid >> 4;
    const int qr = tid >> 2, chunk = tid & 3;
    const float scale = 0.08838834764831845f;

    for (int kb = 0; kb <= qb; kb++) {
        __syncthreads();
#pragma unroll
        for (int i = 0; i < 8; i++) {
            int lin = tid + i * 256;
            int r = lin >> 5, c4 = lin & 31;
            float4 kv = *(const float4*)&Kh[(size_t)(kb * 64 + r) * KVD + c4 * 4];
            Kst[(c4 * 4 + 0) * 68 + r] = kv.x;
            Kst[(c4 * 4 + 1) * 68 + r] = kv.y;
            Kst[(c4 * 4 + 2) * 68 + r] = kv.z;
            Kst[(c4 * 4 + 3) * 68 + r] = kv.w;
            float4 vv = *(const float4*)&Vh[(size_t)(kb * 64 + r) * KVD + c4 * 4];
            *(float4*)&Vs[r * 132 + c4 * 4] = vv;
        }
        __syncthreads();

        float sreg[4][4];
#pragma unroll
        for (int i = 0; i < 4; i++)
#pragma unroll
            for (int j = 0; j < 4; j++) sreg[i][j] = 0.f;
#pragma unroll 8
        for (int kk = 0; kk < 128; kk++) {
            float4 av = *(const float4*)&Qst[kk * 68 + ty * 4];
            float4 bv = *(const float4*)&Kst[kk * 68 + tx * 4];
            float a[4] = {av.x, av.y, av.z, av.w};
            float b[4] = {bv.x, bv.y, bv.z, bv.w};
#pragma unroll
            for (int i = 0; i < 4; i++)
#pragma unroll
                for (int j = 0; j < 4; j++)
                    sreg[i][j] = fmaf(a[i], b[j], sreg[i][j]);
        }
        bool diag = (kb == qb);
#pragma unroll
        for (int i = 0; i < 4; i++)
#pragma unroll
            for (int j = 0; j < 4; j++) {
                float sv = sreg[i][j] * scale;
                if (diag && (tx * 4 + j) > (ty * 4 + i)) sv = -1e30f;
                sreg[i][j] = sv;
                Ss[(ty * 4 + i) * 65 + tx * 4 + j] = sv;
            }
        __syncthreads();

        if (tid < 64) {
            float mx = -1e30f;
            for (int c = 0; c < 64; c++) mx = fmaxf(mx, Ss[tid * 65 + c]);
            float mo = mrow[tid];
            float mn = fmaxf(mo, mx);
            mnew[tid] = mn;
            fsc[tid] = __expf(mo - mn);
        }
        __syncthreads();

        float psum[4] = {0.f, 0.f, 0.f, 0.f};
#pragma unroll
        for (int i = 0; i < 4; i++) {
            float mn = mnew[ty * 4 + i];
#pragma unroll
            for (int j = 0; j < 4; j++) {
                float p = __expf(sreg[i][j] - mn);
                Ss[(ty * 4 + i) * 65 + tx * 4 + j] = p;
                psum[i] += p;
            }
        }
#pragma unroll
        for (int i = 0; i < 4; i++) part[(ty * 4 + i) * 17 + tx] = psum[i];
        __syncthreads();

        if (tid < 64) {
            float s = 0.f;
            for (int x = 0; x < 16; x++) s += part[tid * 17 + x];
            lrow[tid] = lrow[tid] * fsc[tid] + s;
            mrow[tid] = mnew[tid];
        }

        float f = fsc[qr];
#pragma unroll
        for (int d = 0; d < 32; d++) acc[d] *= f;
        for (int kkk = 0; kkk < 64; kkk++) {
            float p = Ss[qr * 65 + kkk];
            const float* vr = &Vs[kkk * 132 + chunk * 32];
#pragma unroll
            for (int dd = 0; dd < 8; dd++) {
                float4 vv = *(const float4*)(vr + dd * 4);
                acc[dd * 4 + 0] = fmaf(p, vv.x, acc[dd * 4 + 0]);
                acc[dd * 4 + 1] = fmaf(p, vv.y, acc[dd * 4 + 1]);
                acc[dd * 4 + 2] = fmaf(p, vv.z, acc[dd * 4 + 2]);
                acc[dd * 4 + 3] = fmaf(p, vv.w, acc[dd * 4 + 3]);
            }
        }
    }
    __syncthreads();
    float linv = 1.f / lrow[qr];
    // tf32-round the attention output so the O-projection GEMM sees RNA operands
    float* op = Og + (size_t)(qb * 64 + qr) * HID + head * HD + chunk * 32;
#pragma unroll
    for (int dd = 0; dd < 8; dd++) {
        float4 o = make_float4(tf32_rna(acc[dd * 4 + 0] * linv),
                               tf32_rna(acc[dd * 4 + 1] * linv),
                               tf32_rna(acc[dd * 4 + 2] * linv),
                               tf32_rna(acc[dd * 4 + 3] * linv));
        *(float4*)(op + dd * 4) = o;
    }
}

// ---------------- launch ----------------
extern "C" void kernel_launch(void* const* d_in, const int* in_sizes, int n_in,
                              void* d_out, int out_size) {
    const float* hs   = (const float*)d_in[0];
    const float* wq   = (const float*)d_in[1];
    const float* wk   = (const float*)d_in[2];
    const float* wv   = (const float*)d_in[3];
    const float* wo   = (const float*)d_in[4];
    const float* scq  = (const float*)d_in[5];
    const float* sck  = (const float*)d_in[6];
    const float* scv  = (const float*)d_in[7];
    const float* sco  = (const float*)d_in[8];
    const float* pqkv = (const float*)d_in[9];
    const float* po   = (const float*)d_in[10];
    const float* cosT = (const float*)d_in[11];
    const float* sinT = (const float*)d_in[12];
    float* out = (float*)d_out;

    float *wmq, *wmk, *wmv, *wmo, *hst, *q, *k, *v, *ao;
    int *ipq, *ipo;
    cudaGetSymbolAddress((void**)&wmq, g_wmq);
    cudaGetSymbolAddress((void**)&wmk, g_wmk);
    cudaGetSymbolAddress((void**)&wmv, g_wmv);
    cudaGetSymbolAddress((void**)&wmo, g_wmo);
    cudaGetSymbolAddress((void**)&hst, g_hst);
    cudaGetSymbolAddress((void**)&q,   g_q);
    cudaGetSymbolAddress((void**)&k,   g_k);
    cudaGetSymbolAddress((void**)&v,   g_v);
    cudaGetSymbolAddress((void**)&ao,  g_ao);
    cudaGetSymbolAddress((void**)&ipq, g_invp_qkv);
    cudaGetSymbolAddress((void**)&ipo, g_invp_o);

    cudaFuncSetAttribute(gemm_tf32, cudaFuncAttributeMaxDynamicSharedMemorySize,
                         GEMM_SMEM_BYTES);
    int fl_smem = FL_SMEM_FLOATS * (int)sizeof(float);
    cudaFuncSetAttribute(flash_kernel, cudaFuncAttributeMaxDynamicSharedMemorySize, fl_smem);

    // Launch order chosen so the 6th launch (ncu -s 5 -c 1) is the big Q GEMM.
    round_tf32<<<(SEQ * HID / 4 + 255) / 256, 256>>>(hs, hst, SEQ * HID / 4);          // 1
    perm_extract<<<(HID * HID + 255) / 256, 256>>>(pqkv, ipq, HID);                    // 2
    mask_weights<<<(HID * (HID / 4) + 255) / 256, 256>>>(wq, scq, ipq, wmq, HID, HID); // 3
    mask_weights<<<(KVD * (HID / 4) + 255) / 256, 256>>>(wk, sck, ipq, wmk, KVD, HID); // 4
    mask_weights<<<(KVD * (HID / 4) + 255) / 256, 256>>>(wv, scv, ipq, wmv, KVD, HID); // 5

    gemm_tf32<<<dim3(HID / 128, SEQ / 128), 256, GEMM_SMEM_BYTES>>>(hst, wmq, q,       // 6 (profiled)
                                                                    SEQ, HID, HID);
    gemm_tf32<<<dim3(KVD / 128, SEQ / 128), 256, GEMM_SMEM_BYTES>>>(hst, wmk, k,
                                                                    SEQ, KVD, HID);
    gemm_tf32<<<dim3(KVD / 128, SEQ / 128), 256, GEMM_SMEM_BYTES>>>(hst, wmv, v,
                                                                    SEQ, KVD, HID);

    perm_extract<<<(HID * HID + 255) / 256, 256>>>(po, ipo, HID);
    mask_weights<<<(HID * (HID / 4) + 255) / 256, 256>>>(wo, sco, ipo, wmo, HID, HID);

    rope_kernel<<<(SEQ * NHEADS * 64 + 255) / 256, 256>>>(q, cosT, sinT, NHEADS);
    rope_kernel<<<(SEQ * NKVH * 64 + 255) / 256, 256>>>(k, cosT, sinT, NKVH);

    flash_kernel<<<dim3(SEQ / 64, NHEADS), 256, fl_smem>>>(q, k, v, ao);

    gemm_tf32<<<dim3(HID / 128, SEQ / 128), 256, GEMM_SMEM_BYTES>>>(ao, wmo, out,
                                                                    SEQ, HID, HID);
}